// round 5
// baseline (speedup 1.0000x reference)
#include <cuda_runtime.h>
#include <math.h>
#include <stdint.h>

// ---------------------------------------------------------------------------
// PK Neural ODE, sm_100a.
// Phase 1: tabulate f(y) = MLP(y) on two uniform grids (parallel, all SMs):
//          fine  : dy = 1/64 over [-1024, 3072)   (1 MB  — hot, L1-cached band)
//          coarse: dy = 1    over [-65536, 65536) (512 KB — guard, L2)
// Phase 2: single-thread sequential dopri5 integration using Catmull-Rom
//          cubic interpolation. Non-finite y short-circuits (no slow path).
// ---------------------------------------------------------------------------

#define NF 262144
#define NC 131072
static __device__ float g_fine[NF];
static __device__ float g_coarse[NC];

static constexpr float Y0F = -1024.0f, DXF = 1.0f / 64.0f, INVDXF = 64.0f;
static constexpr float Y0C = -65536.0f, DXC = 1.0f,        INVDXC = 1.0f;

// Dormand-Prince 5(4) tableau
static constexpr float A21 = (float)(1.0/5.0);
static constexpr float A31 = (float)(3.0/40.0),      A32 = (float)(9.0/40.0);
static constexpr float A41 = (float)(44.0/45.0),     A42 = (float)(-56.0/15.0),    A43 = (float)(32.0/9.0);
static constexpr float A51 = (float)(19372.0/6561.0),A52 = (float)(-25360.0/2187.0),
                       A53 = (float)(64448.0/6561.0),A54 = (float)(-212.0/729.0);
static constexpr float A61 = (float)(9017.0/3168.0), A62 = (float)(-355.0/33.0),
                       A63 = (float)(46732.0/5247.0),A64 = (float)(49.0/176.0),
                       A65 = (float)(-5103.0/18656.0);
static constexpr float B1 = (float)(35.0/384.0),  B3 = (float)(500.0/1113.0),
                       B4 = (float)(125.0/192.0), B5 = (float)(-2187.0/6784.0),
                       B6 = (float)(11.0/84.0);

__device__ __forceinline__ float siluf(float x) {
    return x / (1.0f + expf(-x));
}

// ---------------------------------------------------------------------------
// Build kernel: 4 warps/block, each warp computes 2 adjacent grid points.
// W2/W3 transposed into SMEM with stride-65 padding (conflict-free both ways).
// ---------------------------------------------------------------------------
__global__ void __launch_bounds__(128)
build_tbl_kernel(float* __restrict__ tbl, int npts, float y0, float dx,
                 const float* __restrict__ W1, const float* __restrict__ b1,
                 const float* __restrict__ W2, const float* __restrict__ b2,
                 const float* __restrict__ W3, const float* __restrict__ b3,
                 const float* __restrict__ W4, const float* __restrict__ b4)
{
    __shared__ float sW1[64], sb1[64], sb2[64], sb3[64], sW4[64];
    __shared__ float sW2T[64 * 65];   // sW2T[j*65 + i] = W2[i*64 + j]
    __shared__ float sW3T[64 * 65];

    const int tid = threadIdx.x;
    if (tid < 64) {
        sW1[tid] = W1[tid];
        sb1[tid] = b1[tid];
        sb2[tid] = b2[tid];
        sb3[tid] = b3[tid];
        sW4[tid] = W4[tid];
    }
    for (int idx = tid; idx < 64 * 64; idx += 128) {
        int r = idx >> 6, c = idx & 63;
        sW2T[c * 65 + r] = W2[idx];
        sW3T[c * 65 + r] = W3[idx];
    }
    __syncthreads();

    const int warp = tid >> 5;
    const int lane = tid & 31;
    const int pt0  = (blockIdx.x * 4 + warp) * 2;
    if (pt0 >= npts) return;

    const float ya = y0 + (float)pt0 * dx;
    const float yb = ya + dx;

    // Layer 1 (lane owns rows lane and lane+32, for both points)
    float a1A = siluf(sW1[lane]      * ya + sb1[lane]);
    float c1A = siluf(sW1[lane + 32] * ya + sb1[lane + 32]);
    float a1B = siluf(sW1[lane]      * yb + sb1[lane]);
    float c1B = siluf(sW1[lane + 32] * yb + sb1[lane + 32]);

    // Layer 2
    float aA = sb2[lane],      bA = sb2[lane + 32];
    float aB = aA,             bB = bA;
    #pragma unroll 4
    for (int j = 0; j < 64; j++) {
        float hA = __shfl_sync(0xffffffffu, (j < 32) ? a1A : c1A, j);
        float hB = __shfl_sync(0xffffffffu, (j < 32) ? a1B : c1B, j);
        float w0 = sW2T[j * 65 + lane];
        float w1 = sW2T[j * 65 + lane + 32];
        aA = fmaf(w0, hA, aA);  bA = fmaf(w1, hA, bA);
        aB = fmaf(w0, hB, aB);  bB = fmaf(w1, hB, bB);
    }
    float a2A = siluf(aA), c2A = siluf(bA);
    float a2B = siluf(aB), c2B = siluf(bB);

    // Layer 3
    aA = sb3[lane];  bA = sb3[lane + 32];
    aB = aA;         bB = bA;
    #pragma unroll 4
    for (int j = 0; j < 64; j++) {
        float hA = __shfl_sync(0xffffffffu, (j < 32) ? a2A : c2A, j);
        float hB = __shfl_sync(0xffffffffu, (j < 32) ? a2B : c2B, j);
        float w0 = sW3T[j * 65 + lane];
        float w1 = sW3T[j * 65 + lane + 32];
        aA = fmaf(w0, hA, aA);  bA = fmaf(w1, hA, bA);
        aB = fmaf(w0, hB, aB);  bB = fmaf(w1, hB, bB);
    }
    float a3A = siluf(aA), c3A = siluf(bA);
    float a3B = siluf(aB), c3B = siluf(bB);

    // Output layer: warp reductions
    float pA = fmaf(sW4[lane], a3A, sW4[lane + 32] * c3A);
    float pB = fmaf(sW4[lane], a3B, sW4[lane + 32] * c3B);
    #pragma unroll
    for (int o = 16; o > 0; o >>= 1) {
        pA += __shfl_xor_sync(0xffffffffu, pA, o);
        pB += __shfl_xor_sync(0xffffffffu, pB, o);
    }

    if (lane == 0) {
        float bb = b4[0];
        tbl[pt0] = pA + bb;
        if (pt0 + 1 < npts) tbl[pt0 + 1] = pB + bb;
    }
}

// ---------------------------------------------------------------------------
// Direct single-thread MLP eval (finite |y| > 65536 only — effectively never).
// ---------------------------------------------------------------------------
__device__ __noinline__ float f_direct(float y,
    const float* __restrict__ W1, const float* __restrict__ b1,
    const float* __restrict__ W2, const float* __restrict__ b2,
    const float* __restrict__ W3, const float* __restrict__ b3,
    const float* __restrict__ W4, const float* __restrict__ b4)
{
    float h1[64], h2[64];
    #pragma unroll 1
    for (int i = 0; i < 64; i++) h1[i] = siluf(W1[i] * y + b1[i]);
    #pragma unroll 1
    for (int i = 0; i < 64; i++) {
        float s = b2[i];
        #pragma unroll 1
        for (int j = 0; j < 64; j++) s = fmaf(W2[i * 64 + j], h1[j], s);
        h2[i] = siluf(s);
    }
    #pragma unroll 1
    for (int i = 0; i < 64; i++) {
        float s = b3[i];
        #pragma unroll 1
        for (int j = 0; j < 64; j++) s = fmaf(W3[i * 64 + j], h2[j], s);
        h1[i] = siluf(s);
    }
    float o = b4[0];
    #pragma unroll 1
    for (int i = 0; i < 64; i++) o = fmaf(W4[i], h1[i], o);
    return o;
}

// Catmull-Rom cubic on a uniform table, exact-fraction index math.
__device__ __forceinline__ float interp_tbl(const float* __restrict__ tbl,
                                            int npts, float y0, float dx,
                                            float invdx, float y)
{
    int i = (int)((y - y0) * invdx);
    i = max(1, min(i, npts - 3));
    // fr computed exactly: yi = y0 + i*dx is exactly representable, and
    // (y - yi) is a nearby-value subtraction (exact); *invdx (pow2) exact.
    float fr = (y - (y0 + (float)i * dx)) * invdx;
    float p0 = __ldg(&tbl[i - 1]);
    float p1 = __ldg(&tbl[i]);
    float p2 = __ldg(&tbl[i + 1]);
    float p3 = __ldg(&tbl[i + 2]);
    float d  = p2 - p1;
    float m1 = 0.5f * (p2 - p0);
    float m2 = 0.5f * (p3 - p1);
    float c2 = fmaf(3.0f, d, -2.0f * m1) - m2;   // 3d - 2m1 - m2
    float c3 = fmaf(-2.0f, d, m1) + m2;          // -2d + m1 + m2
    return fmaf(fr, fmaf(fr, fmaf(fr, c3, c2), m1), p1);
}

__device__ __forceinline__ float f_eval(float y,
    const float* __restrict__ W1, const float* __restrict__ b1,
    const float* __restrict__ W2, const float* __restrict__ b2,
    const float* __restrict__ W3, const float* __restrict__ b3,
    const float* __restrict__ W4, const float* __restrict__ b4)
{
    // Fine tier: common case, interior-valid range
    if (y >= Y0F + DXF && y < Y0F + (float)(NF - 2) * DXF)
        return interp_tbl(g_fine, NF, Y0F, DXF, INVDXF, y);
    // Coarse guard tier
    if (y >= Y0C + DXC && y < Y0C + (float)(NC - 2) * DXC)
        return interp_tbl(g_coarse, NC, Y0C, DXC, INVDXC, y);
    // Non-finite: propagate fast (NO slow path — prevents timeout)
    if (!isfinite(y)) return y;
    // Finite but astronomically out of range: exact eval (bounded cost)
    return f_direct(y, W1, b1, W2, b2, W3, b3, W4, b4);
}

// ---------------------------------------------------------------------------
// Sequential solve: single thread. Exact event/dose semantics of reference.
// ---------------------------------------------------------------------------
__global__ void solve_kernel(
    const float* __restrict__ times, int n_times,
    const float* __restrict__ dtimes, int n_dose,
    const float* __restrict__ amounts,
    const float* __restrict__ log_eff,
    const float* __restrict__ W1, const float* __restrict__ b1,
    const float* __restrict__ W2, const float* __restrict__ b2,
    const float* __restrict__ W3, const float* __restrict__ b3,
    const float* __restrict__ W4, const float* __restrict__ b4,
    float* __restrict__ out)
{
    if (threadIdx.x != 0 || blockIdx.x != 0) return;

    const float eff = expf(log_eff[0]);
    const float p10 = powf(10.0f, (float)(n_dose - 1));

    float dt_c[32], da_c[32];
    int nd = n_dose > 32 ? 32 : n_dose;
    for (int d = 0; d < nd; d++) { dt_c[d] = dtimes[d]; da_c[d] = amounts[d]; }

    float y = 0.0f;
    for (int n = 0; n < n_times; n++) {
        float t = times[n];

        // EventFunc: prod(t - dose_times) / 10^(n_dose-1); fires when ~0
        float prod = 1.0f;
        #pragma unroll 1
        for (int d = 0; d < nd; d++) prod *= (t - dt_c[d]);
        prod /= p10;
        if (fabsf(prod) < 1e-6f) {
            float dose = 0.0f;
            #pragma unroll 1
            for (int d = 0; d < nd; d++)
                if (fabsf(t - dt_c[d]) < 1e-6f) dose += da_c[d];
            y += dose * eff;
        }
        out[n] = y;

        float dt = (n + 1 < n_times) ? (times[n + 1] - t) : 0.0f;
        if (dt != 0.0f) {
            float h = dt * (1.0f / 16.0f);
            #pragma unroll 1
            for (int s = 0; s < 16; s++) {
                float k1 = f_eval(y, W1, b1, W2, b2, W3, b3, W4, b4);
                float k2 = f_eval(y + h * (A21 * k1),
                                  W1, b1, W2, b2, W3, b3, W4, b4);
                float k3 = f_eval(y + h * (A31 * k1 + A32 * k2),
                                  W1, b1, W2, b2, W3, b3, W4, b4);
                float k4 = f_eval(y + h * (A41 * k1 + A42 * k2 + A43 * k3),
                                  W1, b1, W2, b2, W3, b3, W4, b4);
                float k5 = f_eval(y + h * (A51 * k1 + A52 * k2 + A53 * k3 + A54 * k4),
                                  W1, b1, W2, b2, W3, b3, W4, b4);
                float k6 = f_eval(y + h * (A61 * k1 + A62 * k2 + A63 * k3 + A64 * k4 + A65 * k5),
                                  W1, b1, W2, b2, W3, b3, W4, b4);
                y = y + h * (B1 * k1 + B3 * k3 + B4 * k4 + B5 * k5 + B6 * k6);
            }
        }
    }
}

// ---------------------------------------------------------------------------
extern "C" void kernel_launch(void* const* d_in, const int* in_sizes, int n_in,
                              void* d_out, int out_size)
{
    const float* times   = (const float*)d_in[0];
    const float* dtimes  = (const float*)d_in[1];
    const float* amounts = (const float*)d_in[2];
    const float* log_eff = (const float*)d_in[3];
    const float* W1 = (const float*)d_in[4];
    const float* b1 = (const float*)d_in[5];
    const float* W2 = (const float*)d_in[6];
    const float* b2 = (const float*)d_in[7];
    const float* W3 = (const float*)d_in[8];
    const float* b3 = (const float*)d_in[9];
    const float* W4 = (const float*)d_in[10];
    const float* b4 = (const float*)d_in[11];

    int n_times = in_sizes[0];
    int n_dose  = in_sizes[1];

    float* fine_ptr   = nullptr;
    float* coarse_ptr = nullptr;
    cudaGetSymbolAddress((void**)&fine_ptr,   g_fine);
    cudaGetSymbolAddress((void**)&coarse_ptr, g_coarse);

    build_tbl_kernel<<<NF / 8, 128>>>(fine_ptr,   NF, Y0F, DXF,
                                      W1, b1, W2, b2, W3, b3, W4, b4);
    build_tbl_kernel<<<NC / 8, 128>>>(coarse_ptr, NC, Y0C, DXC,
                                      W1, b1, W2, b2, W3, b3, W4, b4);
    solve_kernel<<<1, 1>>>(times, n_times, dtimes, n_dose, amounts, log_eff,
                           W1, b1, W2, b2, W3, b3, W4, b4, (float*)d_out);
}

// round 6
// speedup vs baseline: 1.0023x; 1.0023x over previous
#include <cuda_runtime.h>
#include <math.h>
#include <stdint.h>

// ---------------------------------------------------------------------------
// PK Neural ODE, sm_100a.
// Phase 1: tabulate f(y) = MLP(y) on two uniform grids (parallel, all SMs):
//          fine  : dy = 1/64 over [-1024, 3072)   (1 MB  — hot, L1-cached band)
//          coarse: dy = 1    over [-65536, 65536) (512 KB — guard, L2)
// Phase 2: single-thread sequential dopri5 integration using Catmull-Rom
//          cubic interpolation. Non-finite y short-circuits (no slow path).
// ---------------------------------------------------------------------------

#define NF 262144
#define NC 131072
static __device__ float g_fine[NF];
static __device__ float g_coarse[NC];

static constexpr float Y0F = -1024.0f, DXF = 1.0f / 64.0f, INVDXF = 64.0f;
static constexpr float Y0C = -65536.0f, DXC = 1.0f,        INVDXC = 1.0f;

// Dormand-Prince 5(4) tableau
static constexpr float A21 = (float)(1.0/5.0);
static constexpr float A31 = (float)(3.0/40.0),      A32 = (float)(9.0/40.0);
static constexpr float A41 = (float)(44.0/45.0),     A42 = (float)(-56.0/15.0),    A43 = (float)(32.0/9.0);
static constexpr float A51 = (float)(19372.0/6561.0),A52 = (float)(-25360.0/2187.0),
                       A53 = (float)(64448.0/6561.0),A54 = (float)(-212.0/729.0);
static constexpr float A61 = (float)(9017.0/3168.0), A62 = (float)(-355.0/33.0),
                       A63 = (float)(46732.0/5247.0),A64 = (float)(49.0/176.0),
                       A65 = (float)(-5103.0/18656.0);
static constexpr float B1 = (float)(35.0/384.0),  B3 = (float)(500.0/1113.0),
                       B4 = (float)(125.0/192.0), B5 = (float)(-2187.0/6784.0),
                       B6 = (float)(11.0/84.0);

__device__ __forceinline__ float siluf(float x) {
    return x / (1.0f + expf(-x));
}

// ---------------------------------------------------------------------------
// Build kernel: 4 warps/block, each warp computes 2 adjacent grid points.
// W2/W3 transposed into SMEM with stride-65 padding (conflict-free both ways).
// ---------------------------------------------------------------------------
__global__ void __launch_bounds__(128)
build_tbl_kernel(float* __restrict__ tbl, int npts, float y0, float dx,
                 const float* __restrict__ W1, const float* __restrict__ b1,
                 const float* __restrict__ W2, const float* __restrict__ b2,
                 const float* __restrict__ W3, const float* __restrict__ b3,
                 const float* __restrict__ W4, const float* __restrict__ b4)
{
    __shared__ float sW1[64], sb1[64], sb2[64], sb3[64], sW4[64];
    __shared__ float sW2T[64 * 65];   // sW2T[j*65 + i] = W2[i*64 + j]
    __shared__ float sW3T[64 * 65];

    const int tid = threadIdx.x;
    if (tid < 64) {
        sW1[tid] = W1[tid];
        sb1[tid] = b1[tid];
        sb2[tid] = b2[tid];
        sb3[tid] = b3[tid];
        sW4[tid] = W4[tid];
    }
    for (int idx = tid; idx < 64 * 64; idx += 128) {
        int r = idx >> 6, c = idx & 63;
        sW2T[c * 65 + r] = W2[idx];
        sW3T[c * 65 + r] = W3[idx];
    }
    __syncthreads();

    const int warp = tid >> 5;
    const int lane = tid & 31;
    const int pt0  = (blockIdx.x * 4 + warp) * 2;
    if (pt0 >= npts) return;

    const float ya = y0 + (float)pt0 * dx;
    const float yb = ya + dx;

    // Layer 1 (lane owns rows lane and lane+32, for both points)
    float a1A = siluf(sW1[lane]      * ya + sb1[lane]);
    float c1A = siluf(sW1[lane + 32] * ya + sb1[lane + 32]);
    float a1B = siluf(sW1[lane]      * yb + sb1[lane]);
    float c1B = siluf(sW1[lane + 32] * yb + sb1[lane + 32]);

    // Layer 2
    float aA = sb2[lane],      bA = sb2[lane + 32];
    float aB = aA,             bB = bA;
    #pragma unroll 4
    for (int j = 0; j < 64; j++) {
        float hA = __shfl_sync(0xffffffffu, (j < 32) ? a1A : c1A, j);
        float hB = __shfl_sync(0xffffffffu, (j < 32) ? a1B : c1B, j);
        float w0 = sW2T[j * 65 + lane];
        float w1 = sW2T[j * 65 + lane + 32];
        aA = fmaf(w0, hA, aA);  bA = fmaf(w1, hA, bA);
        aB = fmaf(w0, hB, aB);  bB = fmaf(w1, hB, bB);
    }
    float a2A = siluf(aA), c2A = siluf(bA);
    float a2B = siluf(aB), c2B = siluf(bB);

    // Layer 3
    aA = sb3[lane];  bA = sb3[lane + 32];
    aB = aA;         bB = bA;
    #pragma unroll 4
    for (int j = 0; j < 64; j++) {
        float hA = __shfl_sync(0xffffffffu, (j < 32) ? a2A : c2A, j);
        float hB = __shfl_sync(0xffffffffu, (j < 32) ? a2B : c2B, j);
        float w0 = sW3T[j * 65 + lane];
        float w1 = sW3T[j * 65 + lane + 32];
        aA = fmaf(w0, hA, aA);  bA = fmaf(w1, hA, bA);
        aB = fmaf(w0, hB, aB);  bB = fmaf(w1, hB, bB);
    }
    float a3A = siluf(aA), c3A = siluf(bA);
    float a3B = siluf(aB), c3B = siluf(bB);

    // Output layer: warp reductions
    float pA = fmaf(sW4[lane], a3A, sW4[lane + 32] * c3A);
    float pB = fmaf(sW4[lane], a3B, sW4[lane + 32] * c3B);
    #pragma unroll
    for (int o = 16; o > 0; o >>= 1) {
        pA += __shfl_xor_sync(0xffffffffu, pA, o);
        pB += __shfl_xor_sync(0xffffffffu, pB, o);
    }

    if (lane == 0) {
        float bb = b4[0];
        tbl[pt0] = pA + bb;
        if (pt0 + 1 < npts) tbl[pt0 + 1] = pB + bb;
    }
}

// ---------------------------------------------------------------------------
// Direct single-thread MLP eval (finite |y| > 65536 only — effectively never).
// ---------------------------------------------------------------------------
__device__ __noinline__ float f_direct(float y,
    const float* __restrict__ W1, const float* __restrict__ b1,
    const float* __restrict__ W2, const float* __restrict__ b2,
    const float* __restrict__ W3, const float* __restrict__ b3,
    const float* __restrict__ W4, const float* __restrict__ b4)
{
    float h1[64], h2[64];
    #pragma unroll 1
    for (int i = 0; i < 64; i++) h1[i] = siluf(W1[i] * y + b1[i]);
    #pragma unroll 1
    for (int i = 0; i < 64; i++) {
        float s = b2[i];
        #pragma unroll 1
        for (int j = 0; j < 64; j++) s = fmaf(W2[i * 64 + j], h1[j], s);
        h2[i] = siluf(s);
    }
    #pragma unroll 1
    for (int i = 0; i < 64; i++) {
        float s = b3[i];
        #pragma unroll 1
        for (int j = 0; j < 64; j++) s = fmaf(W3[i * 64 + j], h2[j], s);
        h1[i] = siluf(s);
    }
    float o = b4[0];
    #pragma unroll 1
    for (int i = 0; i < 64; i++) o = fmaf(W4[i], h1[i], o);
    return o;
}

// Catmull-Rom cubic on a uniform table, exact-fraction index math.
__device__ __forceinline__ float interp_tbl(const float* __restrict__ tbl,
                                            int npts, float y0, float dx,
                                            float invdx, float y)
{
    int i = (int)((y - y0) * invdx);
    i = max(1, min(i, npts - 3));
    // fr computed exactly: yi = y0 + i*dx is exactly representable, and
    // (y - yi) is a nearby-value subtraction (exact); *invdx (pow2) exact.
    float fr = (y - (y0 + (float)i * dx)) * invdx;
    float p0 = __ldg(&tbl[i - 1]);
    float p1 = __ldg(&tbl[i]);
    float p2 = __ldg(&tbl[i + 1]);
    float p3 = __ldg(&tbl[i + 2]);
    float d  = p2 - p1;
    float m1 = 0.5f * (p2 - p0);
    float m2 = 0.5f * (p3 - p1);
    float c2 = fmaf(3.0f, d, -2.0f * m1) - m2;   // 3d - 2m1 - m2
    float c3 = fmaf(-2.0f, d, m1) + m2;          // -2d + m1 + m2
    return fmaf(fr, fmaf(fr, fmaf(fr, c3, c2), m1), p1);
}

__device__ __forceinline__ float f_eval(float y,
    const float* __restrict__ W1, const float* __restrict__ b1,
    const float* __restrict__ W2, const float* __restrict__ b2,
    const float* __restrict__ W3, const float* __restrict__ b3,
    const float* __restrict__ W4, const float* __restrict__ b4)
{
    // Fine tier: common case, interior-valid range
    if (y >= Y0F + DXF && y < Y0F + (float)(NF - 2) * DXF)
        return interp_tbl(g_fine, NF, Y0F, DXF, INVDXF, y);
    // Coarse guard tier
    if (y >= Y0C + DXC && y < Y0C + (float)(NC - 2) * DXC)
        return interp_tbl(g_coarse, NC, Y0C, DXC, INVDXC, y);
    // Non-finite: propagate fast (NO slow path — prevents timeout)
    if (!isfinite(y)) return y;
    // Finite but astronomically out of range: exact eval (bounded cost)
    return f_direct(y, W1, b1, W2, b2, W3, b3, W4, b4);
}

// ---------------------------------------------------------------------------
// Sequential solve: single thread. Exact event/dose semantics of reference.
// ---------------------------------------------------------------------------
__global__ void solve_kernel(
    const float* __restrict__ times, int n_times,
    const float* __restrict__ dtimes, int n_dose,
    const float* __restrict__ amounts,
    const float* __restrict__ log_eff,
    const float* __restrict__ W1, const float* __restrict__ b1,
    const float* __restrict__ W2, const float* __restrict__ b2,
    const float* __restrict__ W3, const float* __restrict__ b3,
    const float* __restrict__ W4, const float* __restrict__ b4,
    float* __restrict__ out)
{
    if (threadIdx.x != 0 || blockIdx.x != 0) return;

    const float eff = expf(log_eff[0]);
    const float p10 = powf(10.0f, (float)(n_dose - 1));

    float dt_c[32], da_c[32];
    int nd = n_dose > 32 ? 32 : n_dose;
    for (int d = 0; d < nd; d++) { dt_c[d] = dtimes[d]; da_c[d] = amounts[d]; }

    float y = 0.0f;
    for (int n = 0; n < n_times; n++) {
        float t = times[n];

        // EventFunc: prod(t - dose_times) / 10^(n_dose-1); fires when ~0
        float prod = 1.0f;
        #pragma unroll 1
        for (int d = 0; d < nd; d++) prod *= (t - dt_c[d]);
        prod /= p10;
        if (fabsf(prod) < 1e-6f) {
            float dose = 0.0f;
            #pragma unroll 1
            for (int d = 0; d < nd; d++)
                if (fabsf(t - dt_c[d]) < 1e-6f) dose += da_c[d];
            y += dose * eff;
        }
        out[n] = y;

        float dt = (n + 1 < n_times) ? (times[n + 1] - t) : 0.0f;
        if (dt != 0.0f) {
            float h = dt * (1.0f / 16.0f);
            #pragma unroll 1
            for (int s = 0; s < 16; s++) {
                float k1 = f_eval(y, W1, b1, W2, b2, W3, b3, W4, b4);
                float k2 = f_eval(y + h * (A21 * k1),
                                  W1, b1, W2, b2, W3, b3, W4, b4);
                float k3 = f_eval(y + h * (A31 * k1 + A32 * k2),
                                  W1, b1, W2, b2, W3, b3, W4, b4);
                float k4 = f_eval(y + h * (A41 * k1 + A42 * k2 + A43 * k3),
                                  W1, b1, W2, b2, W3, b3, W4, b4);
                float k5 = f_eval(y + h * (A51 * k1 + A52 * k2 + A53 * k3 + A54 * k4),
                                  W1, b1, W2, b2, W3, b3, W4, b4);
                float k6 = f_eval(y + h * (A61 * k1 + A62 * k2 + A63 * k3 + A64 * k4 + A65 * k5),
                                  W1, b1, W2, b2, W3, b3, W4, b4);
                y = y + h * (B1 * k1 + B3 * k3 + B4 * k4 + B5 * k5 + B6 * k6);
            }
        }
    }
}

// ---------------------------------------------------------------------------
extern "C" void kernel_launch(void* const* d_in, const int* in_sizes, int n_in,
                              void* d_out, int out_size)
{
    const float* times   = (const float*)d_in[0];
    const float* dtimes  = (const float*)d_in[1];
    const float* amounts = (const float*)d_in[2];
    const float* log_eff = (const float*)d_in[3];
    const float* W1 = (const float*)d_in[4];
    const float* b1 = (const float*)d_in[5];
    const float* W2 = (const float*)d_in[6];
    const float* b2 = (const float*)d_in[7];
    const float* W3 = (const float*)d_in[8];
    const float* b3 = (const float*)d_in[9];
    const float* W4 = (const float*)d_in[10];
    const float* b4 = (const float*)d_in[11];

    int n_times = in_sizes[0];
    int n_dose  = in_sizes[1];

    float* fine_ptr   = nullptr;
    float* coarse_ptr = nullptr;
    cudaGetSymbolAddress((void**)&fine_ptr,   g_fine);
    cudaGetSymbolAddress((void**)&coarse_ptr, g_coarse);

    build_tbl_kernel<<<NF / 8, 128>>>(fine_ptr,   NF, Y0F, DXF,
                                      W1, b1, W2, b2, W3, b3, W4, b4);
    build_tbl_kernel<<<NC / 8, 128>>>(coarse_ptr, NC, Y0C, DXC,
                                      W1, b1, W2, b2, W3, b3, W4, b4);
    solve_kernel<<<1, 1>>>(times, n_times, dtimes, n_dose, amounts, log_eff,
                           W1, b1, W2, b2, W3, b3, W4, b4, (float*)d_out);
}

// round 7
// speedup vs baseline: 1.0023x; 1.0000x over previous
#include <cuda_runtime.h>
#include <math.h>
#include <stdint.h>

// ---------------------------------------------------------------------------
// PK Neural ODE, sm_100a.
// Phase 1: tabulate f(y) = MLP(y) on two uniform grids (parallel, all SMs):
//          fine  : dy = 1/64 over [-1024, 3072)   (1 MB  — hot, L1-cached band)
//          coarse: dy = 1    over [-65536, 65536) (512 KB — guard, L2)
// Phase 2: single-thread sequential dopri5 integration using Catmull-Rom
//          cubic interpolation. Non-finite y short-circuits (no slow path).
// ---------------------------------------------------------------------------

#define NF 262144
#define NC 131072
static __device__ float g_fine[NF];
static __device__ float g_coarse[NC];

static constexpr float Y0F = -1024.0f, DXF = 1.0f / 64.0f, INVDXF = 64.0f;
static constexpr float Y0C = -65536.0f, DXC = 1.0f,        INVDXC = 1.0f;

// Dormand-Prince 5(4) tableau
static constexpr float A21 = (float)(1.0/5.0);
static constexpr float A31 = (float)(3.0/40.0),      A32 = (float)(9.0/40.0);
static constexpr float A41 = (float)(44.0/45.0),     A42 = (float)(-56.0/15.0),    A43 = (float)(32.0/9.0);
static constexpr float A51 = (float)(19372.0/6561.0),A52 = (float)(-25360.0/2187.0),
                       A53 = (float)(64448.0/6561.0),A54 = (float)(-212.0/729.0);
static constexpr float A61 = (float)(9017.0/3168.0), A62 = (float)(-355.0/33.0),
                       A63 = (float)(46732.0/5247.0),A64 = (float)(49.0/176.0),
                       A65 = (float)(-5103.0/18656.0);
static constexpr float B1 = (float)(35.0/384.0),  B3 = (float)(500.0/1113.0),
                       B4 = (float)(125.0/192.0), B5 = (float)(-2187.0/6784.0),
                       B6 = (float)(11.0/84.0);

__device__ __forceinline__ float siluf(float x) {
    return x / (1.0f + expf(-x));
}

// ---------------------------------------------------------------------------
// Build kernel: 4 warps/block, each warp computes 2 adjacent grid points.
// W2/W3 transposed into SMEM with stride-65 padding (conflict-free both ways).
// ---------------------------------------------------------------------------
__global__ void __launch_bounds__(128)
build_tbl_kernel(float* __restrict__ tbl, int npts, float y0, float dx,
                 const float* __restrict__ W1, const float* __restrict__ b1,
                 const float* __restrict__ W2, const float* __restrict__ b2,
                 const float* __restrict__ W3, const float* __restrict__ b3,
                 const float* __restrict__ W4, const float* __restrict__ b4)
{
    __shared__ float sW1[64], sb1[64], sb2[64], sb3[64], sW4[64];
    __shared__ float sW2T[64 * 65];   // sW2T[j*65 + i] = W2[i*64 + j]
    __shared__ float sW3T[64 * 65];

    const int tid = threadIdx.x;
    if (tid < 64) {
        sW1[tid] = W1[tid];
        sb1[tid] = b1[tid];
        sb2[tid] = b2[tid];
        sb3[tid] = b3[tid];
        sW4[tid] = W4[tid];
    }
    for (int idx = tid; idx < 64 * 64; idx += 128) {
        int r = idx >> 6, c = idx & 63;
        sW2T[c * 65 + r] = W2[idx];
        sW3T[c * 65 + r] = W3[idx];
    }
    __syncthreads();

    const int warp = tid >> 5;
    const int lane = tid & 31;
    const int pt0  = (blockIdx.x * 4 + warp) * 2;
    if (pt0 >= npts) return;

    const float ya = y0 + (float)pt0 * dx;
    const float yb = ya + dx;

    // Layer 1 (lane owns rows lane and lane+32, for both points)
    float a1A = siluf(sW1[lane]      * ya + sb1[lane]);
    float c1A = siluf(sW1[lane + 32] * ya + sb1[lane + 32]);
    float a1B = siluf(sW1[lane]      * yb + sb1[lane]);
    float c1B = siluf(sW1[lane + 32] * yb + sb1[lane + 32]);

    // Layer 2
    float aA = sb2[lane],      bA = sb2[lane + 32];
    float aB = aA,             bB = bA;
    #pragma unroll 4
    for (int j = 0; j < 64; j++) {
        float hA = __shfl_sync(0xffffffffu, (j < 32) ? a1A : c1A, j);
        float hB = __shfl_sync(0xffffffffu, (j < 32) ? a1B : c1B, j);
        float w0 = sW2T[j * 65 + lane];
        float w1 = sW2T[j * 65 + lane + 32];
        aA = fmaf(w0, hA, aA);  bA = fmaf(w1, hA, bA);
        aB = fmaf(w0, hB, aB);  bB = fmaf(w1, hB, bB);
    }
    float a2A = siluf(aA), c2A = siluf(bA);
    float a2B = siluf(aB), c2B = siluf(bB);

    // Layer 3
    aA = sb3[lane];  bA = sb3[lane + 32];
    aB = aA;         bB = bA;
    #pragma unroll 4
    for (int j = 0; j < 64; j++) {
        float hA = __shfl_sync(0xffffffffu, (j < 32) ? a2A : c2A, j);
        float hB = __shfl_sync(0xffffffffu, (j < 32) ? a2B : c2B, j);
        float w0 = sW3T[j * 65 + lane];
        float w1 = sW3T[j * 65 + lane + 32];
        aA = fmaf(w0, hA, aA);  bA = fmaf(w1, hA, bA);
        aB = fmaf(w0, hB, aB);  bB = fmaf(w1, hB, bB);
    }
    float a3A = siluf(aA), c3A = siluf(bA);
    float a3B = siluf(aB), c3B = siluf(bB);

    // Output layer: warp reductions
    float pA = fmaf(sW4[lane], a3A, sW4[lane + 32] * c3A);
    float pB = fmaf(sW4[lane], a3B, sW4[lane + 32] * c3B);
    #pragma unroll
    for (int o = 16; o > 0; o >>= 1) {
        pA += __shfl_xor_sync(0xffffffffu, pA, o);
        pB += __shfl_xor_sync(0xffffffffu, pB, o);
    }

    if (lane == 0) {
        float bb = b4[0];
        tbl[pt0] = pA + bb;
        if (pt0 + 1 < npts) tbl[pt0 + 1] = pB + bb;
    }
}

// ---------------------------------------------------------------------------
// Direct single-thread MLP eval (finite |y| > 65536 only — effectively never).
// ---------------------------------------------------------------------------
__device__ __noinline__ float f_direct(float y,
    const float* __restrict__ W1, const float* __restrict__ b1,
    const float* __restrict__ W2, const float* __restrict__ b2,
    const float* __restrict__ W3, const float* __restrict__ b3,
    const float* __restrict__ W4, const float* __restrict__ b4)
{
    float h1[64], h2[64];
    #pragma unroll 1
    for (int i = 0; i < 64; i++) h1[i] = siluf(W1[i] * y + b1[i]);
    #pragma unroll 1
    for (int i = 0; i < 64; i++) {
        float s = b2[i];
        #pragma unroll 1
        for (int j = 0; j < 64; j++) s = fmaf(W2[i * 64 + j], h1[j], s);
        h2[i] = siluf(s);
    }
    #pragma unroll 1
    for (int i = 0; i < 64; i++) {
        float s = b3[i];
        #pragma unroll 1
        for (int j = 0; j < 64; j++) s = fmaf(W3[i * 64 + j], h2[j], s);
        h1[i] = siluf(s);
    }
    float o = b4[0];
    #pragma unroll 1
    for (int i = 0; i < 64; i++) o = fmaf(W4[i], h1[i], o);
    return o;
}

// Catmull-Rom cubic on a uniform table, exact-fraction index math.
__device__ __forceinline__ float interp_tbl(const float* __restrict__ tbl,
                                            int npts, float y0, float dx,
                                            float invdx, float y)
{
    int i = (int)((y - y0) * invdx);
    i = max(1, min(i, npts - 3));
    // fr computed exactly: yi = y0 + i*dx is exactly representable, and
    // (y - yi) is a nearby-value subtraction (exact); *invdx (pow2) exact.
    float fr = (y - (y0 + (float)i * dx)) * invdx;
    float p0 = __ldg(&tbl[i - 1]);
    float p1 = __ldg(&tbl[i]);
    float p2 = __ldg(&tbl[i + 1]);
    float p3 = __ldg(&tbl[i + 2]);
    float d  = p2 - p1;
    float m1 = 0.5f * (p2 - p0);
    float m2 = 0.5f * (p3 - p1);
    float c2 = fmaf(3.0f, d, -2.0f * m1) - m2;   // 3d - 2m1 - m2
    float c3 = fmaf(-2.0f, d, m1) + m2;          // -2d + m1 + m2
    return fmaf(fr, fmaf(fr, fmaf(fr, c3, c2), m1), p1);
}

__device__ __forceinline__ float f_eval(float y,
    const float* __restrict__ W1, const float* __restrict__ b1,
    const float* __restrict__ W2, const float* __restrict__ b2,
    const float* __restrict__ W3, const float* __restrict__ b3,
    const float* __restrict__ W4, const float* __restrict__ b4)
{
    // Fine tier: common case, interior-valid range
    if (y >= Y0F + DXF && y < Y0F + (float)(NF - 2) * DXF)
        return interp_tbl(g_fine, NF, Y0F, DXF, INVDXF, y);
    // Coarse guard tier
    if (y >= Y0C + DXC && y < Y0C + (float)(NC - 2) * DXC)
        return interp_tbl(g_coarse, NC, Y0C, DXC, INVDXC, y);
    // Non-finite: propagate fast (NO slow path — prevents timeout)
    if (!isfinite(y)) return y;
    // Finite but astronomically out of range: exact eval (bounded cost)
    return f_direct(y, W1, b1, W2, b2, W3, b3, W4, b4);
}

// ---------------------------------------------------------------------------
// Sequential solve: single thread. Exact event/dose semantics of reference.
// ---------------------------------------------------------------------------
__global__ void solve_kernel(
    const float* __restrict__ times, int n_times,
    const float* __restrict__ dtimes, int n_dose,
    const float* __restrict__ amounts,
    const float* __restrict__ log_eff,
    const float* __restrict__ W1, const float* __restrict__ b1,
    const float* __restrict__ W2, const float* __restrict__ b2,
    const float* __restrict__ W3, const float* __restrict__ b3,
    const float* __restrict__ W4, const float* __restrict__ b4,
    float* __restrict__ out)
{
    if (threadIdx.x != 0 || blockIdx.x != 0) return;

    const float eff = expf(log_eff[0]);
    const float p10 = powf(10.0f, (float)(n_dose - 1));

    float dt_c[32], da_c[32];
    int nd = n_dose > 32 ? 32 : n_dose;
    for (int d = 0; d < nd; d++) { dt_c[d] = dtimes[d]; da_c[d] = amounts[d]; }

    float y = 0.0f;
    for (int n = 0; n < n_times; n++) {
        float t = times[n];

        // EventFunc: prod(t - dose_times) / 10^(n_dose-1); fires when ~0
        float prod = 1.0f;
        #pragma unroll 1
        for (int d = 0; d < nd; d++) prod *= (t - dt_c[d]);
        prod /= p10;
        if (fabsf(prod) < 1e-6f) {
            float dose = 0.0f;
            #pragma unroll 1
            for (int d = 0; d < nd; d++)
                if (fabsf(t - dt_c[d]) < 1e-6f) dose += da_c[d];
            y += dose * eff;
        }
        out[n] = y;

        float dt = (n + 1 < n_times) ? (times[n + 1] - t) : 0.0f;
        if (dt != 0.0f) {
            float h = dt * (1.0f / 16.0f);
            #pragma unroll 1
            for (int s = 0; s < 16; s++) {
                float k1 = f_eval(y, W1, b1, W2, b2, W3, b3, W4, b4);
                float k2 = f_eval(y + h * (A21 * k1),
                                  W1, b1, W2, b2, W3, b3, W4, b4);
                float k3 = f_eval(y + h * (A31 * k1 + A32 * k2),
                                  W1, b1, W2, b2, W3, b3, W4, b4);
                float k4 = f_eval(y + h * (A41 * k1 + A42 * k2 + A43 * k3),
                                  W1, b1, W2, b2, W3, b3, W4, b4);
                float k5 = f_eval(y + h * (A51 * k1 + A52 * k2 + A53 * k3 + A54 * k4),
                                  W1, b1, W2, b2, W3, b3, W4, b4);
                float k6 = f_eval(y + h * (A61 * k1 + A62 * k2 + A63 * k3 + A64 * k4 + A65 * k5),
                                  W1, b1, W2, b2, W3, b3, W4, b4);
                y = y + h * (B1 * k1 + B3 * k3 + B4 * k4 + B5 * k5 + B6 * k6);
            }
        }
    }
}

// ---------------------------------------------------------------------------
extern "C" void kernel_launch(void* const* d_in, const int* in_sizes, int n_in,
                              void* d_out, int out_size)
{
    const float* times   = (const float*)d_in[0];
    const float* dtimes  = (const float*)d_in[1];
    const float* amounts = (const float*)d_in[2];
    const float* log_eff = (const float*)d_in[3];
    const float* W1 = (const float*)d_in[4];
    const float* b1 = (const float*)d_in[5];
    const float* W2 = (const float*)d_in[6];
    const float* b2 = (const float*)d_in[7];
    const float* W3 = (const float*)d_in[8];
    const float* b3 = (const float*)d_in[9];
    const float* W4 = (const float*)d_in[10];
    const float* b4 = (const float*)d_in[11];

    int n_times = in_sizes[0];
    int n_dose  = in_sizes[1];

    float* fine_ptr   = nullptr;
    float* coarse_ptr = nullptr;
    cudaGetSymbolAddress((void**)&fine_ptr,   g_fine);
    cudaGetSymbolAddress((void**)&coarse_ptr, g_coarse);

    build_tbl_kernel<<<NF / 8, 128>>>(fine_ptr,   NF, Y0F, DXF,
                                      W1, b1, W2, b2, W3, b3, W4, b4);
    build_tbl_kernel<<<NC / 8, 128>>>(coarse_ptr, NC, Y0C, DXC,
                                      W1, b1, W2, b2, W3, b3, W4, b4);
    solve_kernel<<<1, 1>>>(times, n_times, dtimes, n_dose, amounts, log_eff,
                           W1, b1, W2, b2, W3, b3, W4, b4, (float*)d_out);
}